// round 12
// baseline (speedup 1.0000x reference)
#include <cuda_runtime.h>
#include <cuda_bf16.h>
#include <cstdint>

#define NTOK   8192
#define INFEAT 128
#define DHEAD  64
#define NHEADS 2
#define MASKW  (NTOK/32)   // 256 words per row

#define BM 128
#define BN 64
#define NTILES (NTOK/BN)   // 128
#define NSPLIT 4
#define TILES_PER_SPLIT (NTILES/NSPLIT)  // 32

// 0.125 * log2(e): fold both the 1/sqrt(64) scale and the exp->exp2 change of base
#define QSCALE 0.1803368801111204f

// attn dynamic smem layout (bytes from base):
//   [0, 16384)          q_s   : BM*DHEAD bf16, swizzled
//   [16384, 32768)      k_s   : 2 x BN*DHEAD bf16
//   [32768, 49152)      v_s   : 2 x BN*DHEAD bf16
//   [49152, 51200)      mask_s: 2 x BM*2 u32
#define SM_Q    0
#define SM_K    16384
#define SM_V    32768
#define SM_MASK 49152
#define SM_TOTAL 51200

__device__ __align__(16) uint32_t      g_adjbits[NTOK * MASKW];              // 8 MB
__device__ __align__(16) __nv_bfloat16 g_q[NHEADS][NTOK][DHEAD];             // 2 MB
__device__ __align__(16) __nv_bfloat16 g_k[NHEADS][NTOK][DHEAD];             // 2 MB
__device__ __align__(16) __nv_bfloat16 g_v[NHEADS][NTOK][DHEAD];             // 2 MB
__device__ __align__(16) float         g_opart[NSPLIT][NHEADS][NTOK][DHEAD]; // 16 MB
__device__ __align__(16) float         g_lpart[NSPLIT][NHEADS][NTOK];        // 256 KB

// ---------------------------------------------------------------------------
// Kernel 1: pack adjacency -> bitmask. Standalone, low-reg, high-occupancy.
// ---------------------------------------------------------------------------
__global__ void __launch_bounds__(256) pack_kernel(const int* __restrict__ adj)
{
    int gwarp = blockIdx.x * 8 + (threadIdx.x >> 5);
    int lane = threadIdx.x & 31;
    long long base = (long long)gwarp * 1024;

    #pragma unroll
    for (int it = 0; it < 2; it++) {
        const int* p = adj + base + it * 512 + lane;
        int v[16];
        #pragma unroll
        for (int j = 0; j < 16; j++) v[j] = p[j * 32];   // MLP=16, 1 line/instr
        uint32_t myword = 0;
        #pragma unroll
        for (int j = 0; j < 16; j++) {
            uint32_t b = __ballot_sync(0xffffffffu, v[j] > 0);
            if (lane == j) myword = b;
        }
        if (lane < 16)
            g_adjbits[gwarp * 32 + it * 16 + lane] = myword;
    }
}

// ---------------------------------------------------------------------------
// Kernel 2: slim projections. 256 thr; block = 16 rows x 256 features.
// f in [0,512): Q(*QSCALE,bf16) | K(bf16) | V(bf16) | skip(fp32 -> d_out)
// ---------------------------------------------------------------------------
__global__ void __launch_bounds__(256) proj_kernel(
    const float* __restrict__ h,
    const float* __restrict__ Wq, const float* __restrict__ bq,
    const float* __restrict__ Wk, const float* __restrict__ bk,
    const float* __restrict__ Wv, const float* __restrict__ bv,
    const float* __restrict__ Ws, const float* __restrict__ bs,
    float* __restrict__ out)
{
    __shared__ float4 h_s[16][32];   // 8 KB
    int tid = threadIdx.x;
    int rowbase = (blockIdx.x >> 1) * 16;
    int fhalf = blockIdx.x & 1;

    const float4* h4 = (const float4*)(h + (long long)rowbase * INFEAT);
    for (int i = tid; i < 16 * 32; i += 256)
        h_s[i >> 5][i & 31] = h4[i];
    __syncthreads();

    int f = fhalf * 256 + tid;           // 0..511
    const float* W; const float* B; int kind, fo;
    if (f < 128)      { W = Wq; B = bq; kind = 0; fo = f; }
    else if (f < 256) { W = Wk; B = bk; kind = 1; fo = f - 128; }
    else if (f < 384) { W = Wv; B = bv; kind = 2; fo = f - 256; }
    else              { W = Ws; B = bs; kind = 3; fo = f - 384; }

    float acc[16];
    float bias = B[fo];
    #pragma unroll
    for (int r = 0; r < 16; r++) acc[r] = bias;

    const float4* Wrow = (const float4*)(W + fo * INFEAT);
    #pragma unroll
    for (int kt = 0; kt < 4; kt++) {
        float4 w[8];
        #pragma unroll
        for (int j = 0; j < 8; j++) w[j] = Wrow[kt * 8 + j];
        #pragma unroll
        for (int r = 0; r < 16; r++) {
            float a = acc[r];
            #pragma unroll
            for (int j = 0; j < 8; j++) {
                float4 hv = h_s[r][kt * 8 + j];
                a += hv.x * w[j].x;
                a += hv.y * w[j].y;
                a += hv.z * w[j].z;
                a += hv.w * w[j].w;
            }
            acc[r] = a;
        }
    }

    int head = fo >> 6, d = fo & 63;
    #pragma unroll
    for (int r = 0; r < 16; r++) {
        int n = rowbase + r;
        if (kind == 0)      g_q[head][n][d] = __float2bfloat16(acc[r] * QSCALE);
        else if (kind == 1) g_k[head][n][d] = __float2bfloat16(acc[r]);
        else if (kind == 2) g_v[head][n][d] = __float2bfloat16(acc[r]);
        else                out[(long long)n * 128 + fo] = acc[r];
    }
}

// ---------------------------------------------------------------------------
// Kernel 3: masked flash attention, BM=128 big-tile, occ 2, split-K x4.
// No-max softmax via ex2 (Q pre-scaled by log2e/8). bf16 mma.sync.
// Dynamic smem (50 KB > 48 KB static limit).
// ---------------------------------------------------------------------------
__device__ __forceinline__ uint32_t s2u(const void* p) {
    return (uint32_t)__cvta_generic_to_shared(p);
}
__device__ __forceinline__ float ex2f(float x) {
    float y; asm("ex2.approx.f32 %0, %1;" : "=f"(y) : "f"(x)); return y;
}

#define CP16(dst, src) asm volatile("cp.async.cg.shared.global [%0], [%1], 16;\n" :: "r"(dst), "l"(src) : "memory")
#define CP8(dst, src)  asm volatile("cp.async.ca.shared.global [%0], [%1], 8;\n"  :: "r"(dst), "l"(src) : "memory")
#define CP_COMMIT()    asm volatile("cp.async.commit_group;\n" ::: "memory")
#define CP_WAIT1()     asm volatile("cp.async.wait_group 1;\n" ::: "memory")
#define CP_WAIT0()     asm volatile("cp.async.wait_group 0;\n" ::: "memory")

__device__ __forceinline__ void ldsm4(uint32_t* d, uint32_t addr) {
    asm volatile("ldmatrix.sync.aligned.m8n8.x4.shared.b16 {%0,%1,%2,%3}, [%4];\n"
        : "=r"(d[0]), "=r"(d[1]), "=r"(d[2]), "=r"(d[3]) : "r"(addr));
}
__device__ __forceinline__ void ldsm4t(uint32_t* d, uint32_t addr) {
    asm volatile("ldmatrix.sync.aligned.m8n8.x4.trans.shared.b16 {%0,%1,%2,%3}, [%4];\n"
        : "=r"(d[0]), "=r"(d[1]), "=r"(d[2]), "=r"(d[3]) : "r"(addr));
}
__device__ __forceinline__ void mma16816(float* c, const uint32_t* a, const uint32_t* b) {
    asm volatile("mma.sync.aligned.m16n8k16.row.col.f32.bf16.bf16.f32 "
        "{%0,%1,%2,%3}, {%4,%5,%6,%7}, {%8,%9}, {%0,%1,%2,%3};\n"
        : "+f"(c[0]), "+f"(c[1]), "+f"(c[2]), "+f"(c[3])
        : "r"(a[0]), "r"(a[1]), "r"(a[2]), "r"(a[3]), "r"(b[0]), "r"(b[1]));
}

extern __shared__ char sm_dyn[];

__global__ void __launch_bounds__(128, 2) attn_kernel()
{
    int mtile = blockIdx.x, head = blockIdx.y, split = blockIdx.z;
    int t0 = split * TILES_PER_SPLIT;
    int tid = threadIdx.x, warp = tid >> 5, lane = tid & 31;
    int g = lane >> 2, t4 = lane & 3;

    char* q_b = sm_dyn + SM_Q;
    char* k_b = sm_dyn + SM_K;     // [2][BN*DHEAD] bf16
    char* v_b = sm_dyn + SM_V;     // [2][BN*DHEAD] bf16
    uint32_t* mask_b = (uint32_t*)(sm_dyn + SM_MASK);  // [2][BM*2]

    // ---- stage Q tile (128 rows x 64, swizzled: 16B chunk ^ (row&7)) ----
    {
        const uint4* qg = (const uint4*)&g_q[head][mtile * BM][0];
        uint4* q4 = (uint4*)q_b;
        for (int i = tid; i < 1024; i += 128) {
            int r = i >> 3, c = i & 7;
            q4[r * 8 + (c ^ (r & 7))] = qg[i];
        }
    }
    __syncthreads();

    // ---- load Q a-frags: warp owns rows warp*32..+32 (2 m-tiles) ----
    uint32_t qf[2][4][4];
    {
        #pragma unroll
        for (int mt = 0; mt < 2; mt++) {
            #pragma unroll
            for (int kt = 0; kt < 4; kt++) {
                int r = warp * 32 + mt * 16 + (lane & 15);
                int kc = kt * 2 + (lane >> 4);
                uint32_t addr = s2u(q_b + r * 128 + ((kc ^ (r & 7)) << 4));
                ldsm4(qf[mt][kt], addr);
            }
        }
    }

    float o[2][8][4];
    #pragma unroll
    for (int mt = 0; mt < 2; mt++)
        #pragma unroll
        for (int j = 0; j < 8; j++)
            { o[mt][j][0] = 0.f; o[mt][j][1] = 0.f; o[mt][j][2] = 0.f; o[mt][j][3] = 0.f; }
    float lsA[2] = {0.f, 0.f}, lsB[2] = {0.f, 0.f};

    // ---- prefetch tile t0 ----
    {
        const uint4* kg = (const uint4*)&g_k[head][t0 * BN][0];
        const uint4* vg = (const uint4*)&g_v[head][t0 * BN][0];
        uint4* ks4 = (uint4*)k_b;
        uint4* vs4 = (uint4*)v_b;
        for (int i = tid; i < 512; i += 128) {
            int r = i >> 3, c = i & 7, dsw = r * 8 + (c ^ (r & 7));
            CP16(s2u(&ks4[dsw]), &kg[i]);
            CP16(s2u(&vs4[dsw]), &vg[i]);
        }
        CP8(s2u(&mask_b[tid * 2]),
            &g_adjbits[(mtile * BM + tid) * MASKW + t0 * 2]);
        CP_COMMIT();
    }

    for (int tt = 0; tt < TILES_PER_SPLIT; tt++) {
        int t = t0 + tt;
        int buf = tt & 1;
        __syncthreads();   // prior compute done before overwriting buf^1
        if (tt + 1 < TILES_PER_SPLIT) {
            int n0 = (t + 1) * BN;
            const uint4* kg = (const uint4*)&g_k[head][n0][0];
            const uint4* vg = (const uint4*)&g_v[head][n0][0];
            uint4* ks4 = (uint4*)(k_b + (buf ^ 1) * (BN * DHEAD * 2));
            uint4* vs4 = (uint4*)(v_b + (buf ^ 1) * (BN * DHEAD * 2));
            for (int i = tid; i < 512; i += 128) {
                int r = i >> 3, c = i & 7, dsw = r * 8 + (c ^ (r & 7));
                CP16(s2u(&ks4[dsw]), &kg[i]);
                CP16(s2u(&vs4[dsw]), &vg[i]);
            }
            CP8(s2u(&mask_b[(buf ^ 1) * (BM * 2) + tid * 2]),
                &g_adjbits[(mtile * BM + tid) * MASKW + (t + 1) * 2]);
            CP_COMMIT();
            CP_WAIT1();
        } else {
            CP_WAIT0();
        }
        __syncthreads();   // tile t fully in smem for all threads

        // ---- S = Q * K^T : K-frags shared across both m-tiles ----
        float sc[2][8][4];
        #pragma unroll
        for (int mt = 0; mt < 2; mt++)
            #pragma unroll
            for (int j = 0; j < 8; j++)
                { sc[mt][j][0] = 0.f; sc[mt][j][1] = 0.f; sc[mt][j][2] = 0.f; sc[mt][j][3] = 0.f; }

        char* kb8 = k_b + buf * (BN * DHEAD * 2);
        #pragma unroll
        for (int kt = 0; kt < 4; kt++) {
            uint32_t kb[8][2];
            #pragma unroll
            for (int p = 0; p < 4; p++) {
                int nrow = p * 16 + (lane & 7) + ((lane & 16) ? 8 : 0);
                int kc = kt * 2 + ((lane & 8) ? 1 : 0);
                uint32_t addr = s2u(kb8 + nrow * 128 + ((kc ^ (nrow & 7)) << 4));
                uint32_t r[4]; ldsm4(r, addr);
                kb[2 * p][0] = r[0]; kb[2 * p][1] = r[1];
                kb[2 * p + 1][0] = r[2]; kb[2 * p + 1][1] = r[3];
            }
            #pragma unroll
            for (int mt = 0; mt < 2; mt++)
                #pragma unroll
                for (int j = 0; j < 8; j++) mma16816(sc[mt][j], qf[mt][kt], kb[j]);
        }

        // ---- masks for this warp's 4 row-groups ----
        uint32_t* mk = mask_b + buf * (BM * 2);
        uint32_t mA0[2], mA1[2], mB0[2], mB1[2];
        #pragma unroll
        for (int mt = 0; mt < 2; mt++) {
            int rA = warp * 32 + mt * 16 + g;
            mA0[mt] = mk[rA * 2];
            mA1[mt] = mk[rA * 2 + 1];
            mB0[mt] = mk[(rA + 8) * 2];
            mB1[mt] = mk[(rA + 8) * 2 + 1];
        }

        // ---- PV loop: exp2/mask folded in per kt, V-frags shared across mt ----
        char* vb8 = v_b + buf * (BN * DHEAD * 2);
        #pragma unroll
        for (int kt = 0; kt < 4; kt++) {
            uint32_t a[2][4];
            #pragma unroll
            for (int mt = 0; mt < 2; mt++) {
                #pragma unroll
                for (int jj = 0; jj < 2; jj++) {
                    int j = 2 * kt + jj;
                    int sh = (j * 8 + t4 * 2) & 31;
                    uint32_t wA = (j < 4) ? mA0[mt] : mA1[mt];
                    uint32_t wB = (j < 4) ? mB0[mt] : mB1[mt];
                    float e0 = ((wA >> sh) & 1)       ? ex2f(sc[mt][j][0]) : 0.f;
                    float e1 = ((wA >> (sh + 1)) & 1) ? ex2f(sc[mt][j][1]) : 0.f;
                    float e2 = ((wB >> sh) & 1)       ? ex2f(sc[mt][j][2]) : 0.f;
                    float e3 = ((wB >> (sh + 1)) & 1) ? ex2f(sc[mt][j][3]) : 0.f;
                    lsA[mt] += e0 + e1;
                    lsB[mt] += e2 + e3;
                    __nv_bfloat162 p01 = __floats2bfloat162_rn(e0, e1);
                    __nv_bfloat162 p23 = __floats2bfloat162_rn(e2, e3);
                    a[mt][2 * jj]     = *(uint32_t*)&p01;
                    a[mt][2 * jj + 1] = *(uint32_t*)&p23;
                }
            }

            uint32_t vb[8][2];
            #pragma unroll
            for (int p = 0; p < 4; p++) {
                int vrow = kt * 16 + (lane & 7) + ((lane & 8) ? 8 : 0);
                int dc = 2 * p + ((lane & 16) ? 1 : 0);
                uint32_t addr = s2u(vb8 + vrow * 128 + ((dc ^ (vrow & 7)) << 4));
                uint32_t r[4]; ldsm4t(r, addr);
                vb[2 * p][0] = r[0]; vb[2 * p][1] = r[1];
                vb[2 * p + 1][0] = r[2]; vb[2 * p + 1][1] = r[3];
            }
            #pragma unroll
            for (int mt = 0; mt < 2; mt++)
                #pragma unroll
                for (int jd = 0; jd < 8; jd++) mma16816(o[mt][jd], a[mt], vb[jd]);
        }
    }

    // ---- store partial O (unnormalized) + row sums to scratch ----
    #pragma unroll
    for (int mt = 0; mt < 2; mt++) {
        lsA[mt] += __shfl_xor_sync(0xffffffffu, lsA[mt], 1);
        lsA[mt] += __shfl_xor_sync(0xffffffffu, lsA[mt], 2);
        lsB[mt] += __shfl_xor_sync(0xffffffffu, lsB[mt], 1);
        lsB[mt] += __shfl_xor_sync(0xffffffffu, lsB[mt], 2);

        int base = mtile * BM + warp * 32 + mt * 16;
        if (t4 == 0) {
            g_lpart[split][head][base + g]     = lsA[mt];
            g_lpart[split][head][base + 8 + g] = lsB[mt];
        }
        #pragma unroll
        for (int jd = 0; jd < 8; jd++) {
            int d = jd * 8 + t4 * 2;
            *(float2*)&g_opart[split][head][base + g][d]     = make_float2(o[mt][jd][0], o[mt][jd][1]);
            *(float2*)&g_opart[split][head][base + 8 + g][d] = make_float2(o[mt][jd][2], o[mt][jd][3]);
        }
    }
}

// ---------------------------------------------------------------------------
// Kernel 4: combine splits, normalize, add skip (already resident in d_out)
// ---------------------------------------------------------------------------
__global__ void __launch_bounds__(256) epilogue_kernel(float* __restrict__ out)
{
    int idx = blockIdx.x * 256 + threadIdx.x;   // float4 index over [8192][128]
    int n = idx >> 5;
    int f4 = idx & 31;
    int head = f4 >> 4;
    int d = (f4 & 15) * 4;

    float4 a = *(const float4*)&g_opart[0][head][n][d];
    float lt = g_lpart[0][head][n];
    #pragma unroll
    for (int s = 1; s < NSPLIT; s++) {
        float4 b = *(const float4*)&g_opart[s][head][n][d];
        a.x += b.x; a.y += b.y; a.z += b.z; a.w += b.w;
        lt += g_lpart[s][head][n];
    }
    float inv = 1.f / lt;
    float4* po = (float4*)out + idx;
    float4 s = *po;
    s.x += a.x * inv;
    s.y += a.y * inv;
    s.z += a.z * inv;
    s.w += a.w * inv;
    *po = s;
}

// ---------------------------------------------------------------------------
extern "C" void kernel_launch(void* const* d_in, const int* in_sizes, int n_in,
                              void* d_out, int out_size)
{
    const float* h   = (const float*)d_in[0];
    const int*   adj = (const int*)d_in[1];
    const float* Wq  = (const float*)d_in[2];
    const float* bq  = (const float*)d_in[3];
    const float* Wk  = (const float*)d_in[4];
    const float* bk  = (const float*)d_in[5];
    const float* Wv  = (const float*)d_in[6];
    const float* bv  = (const float*)d_in[7];
    const float* Ws  = (const float*)d_in[8];
    const float* bs  = (const float*)d_in[9];
    float* out = (float*)d_out;

    // opt in to >48KB dynamic smem for the attention kernel (idempotent,
    // host-side attribute set; not an allocation, graph-capture-safe)
    cudaFuncSetAttribute(attn_kernel,
                         cudaFuncAttributeMaxDynamicSharedMemorySize, SM_TOTAL);

    // 1) pack adjacency bitmask (high-occupancy, low-reg)
    pack_kernel<<<NTOK * MASKW / (8 * 32), 256>>>(adj);

    // 2) slim projections (writes skip into d_out, Q/K/V to device buffers)
    proj_kernel<<<1024, 256>>>(h, Wq, bq, Wk, bk, Wv, bv, Ws, bs, out);

    // 3) big-tile masked flash attention, split-K x4, partials to scratch
    dim3 grid(NTOK / BM, NHEADS, NSPLIT);
    attn_kernel<<<grid, 128, SM_TOTAL>>>();

    // 4) combine + normalize + skip
    epilogue_kernel<<<(NTOK * 128 / 4) / 256, 256>>>(out);
}

// round 15
// speedup vs baseline: 1.0687x; 1.0687x over previous
#include <cuda_runtime.h>
#include <cuda_bf16.h>
#include <cstdint>

#define NTOK   8192
#define INFEAT 128
#define DHEAD  64
#define NHEADS 2
#define MASKW  (NTOK/32)   // 256 words per row

#define BM 64
#define BN 64
#define NTILES (NTOK/BN)   // 128
#define NSPLIT 4
#define TILES_PER_SPLIT (NTILES/NSPLIT)  // 32

// 0.125 * log2(e): folds the 1/sqrt(64) scale and the exp->exp2 change of base
#define QSCALE 0.1803368801111204f

__device__ __align__(16) uint32_t      g_adjbits[NTOK * MASKW];              // 8 MB
__device__ __align__(16) __nv_bfloat16 g_q[NHEADS][NTOK][DHEAD];             // 2 MB
__device__ __align__(16) __nv_bfloat16 g_k[NHEADS][NTOK][DHEAD];             // 2 MB
__device__ __align__(16) __nv_bfloat16 g_v[NHEADS][NTOK][DHEAD];             // 2 MB
__device__ __align__(16) float         g_opart[NSPLIT][NHEADS][NTOK][DHEAD]; // 16 MB
__device__ __align__(16) float         g_lpart[NSPLIT][NHEADS][NTOK];        // 256 KB

// ---------------------------------------------------------------------------
// Kernel 1: pack adjacency -> bitmask. Standalone, low-reg, high-occupancy.
// ---------------------------------------------------------------------------
__global__ void __launch_bounds__(256) pack_kernel(const int* __restrict__ adj)
{
    int gwarp = blockIdx.x * 8 + (threadIdx.x >> 5);
    int lane = threadIdx.x & 31;
    long long base = (long long)gwarp * 1024;

    #pragma unroll
    for (int it = 0; it < 2; it++) {
        const int* p = adj + base + it * 512 + lane;
        int v[16];
        #pragma unroll
        for (int j = 0; j < 16; j++) v[j] = p[j * 32];   // MLP=16, 1 line/instr
        uint32_t myword = 0;
        #pragma unroll
        for (int j = 0; j < 16; j++) {
            uint32_t b = __ballot_sync(0xffffffffu, v[j] > 0);
            if (lane == j) myword = b;
        }
        if (lane < 16)
            g_adjbits[gwarp * 32 + it * 16 + lane] = myword;
    }
}

// ---------------------------------------------------------------------------
// Kernel 2: slim projections. 256 thr; block = 16 rows x 256 features.
// f in [0,512): Q(*QSCALE,bf16) | K(bf16) | V(bf16) | skip(fp32 -> d_out)
// ---------------------------------------------------------------------------
__global__ void __launch_bounds__(256) proj_kernel(
    const float* __restrict__ h,
    const float* __restrict__ Wq, const float* __restrict__ bq,
    const float* __restrict__ Wk, const float* __restrict__ bk,
    const float* __restrict__ Wv, const float* __restrict__ bv,
    const float* __restrict__ Ws, const float* __restrict__ bs,
    float* __restrict__ out)
{
    __shared__ float4 h_s[16][32];   // 8 KB
    int tid = threadIdx.x;
    int rowbase = (blockIdx.x >> 1) * 16;
    int fhalf = blockIdx.x & 1;

    const float4* h4 = (const float4*)(h + (long long)rowbase * INFEAT);
    for (int i = tid; i < 16 * 32; i += 256)
        h_s[i >> 5][i & 31] = h4[i];
    __syncthreads();

    int f = fhalf * 256 + tid;           // 0..511
    const float* W; const float* B; int kind, fo;
    if (f < 128)      { W = Wq; B = bq; kind = 0; fo = f; }
    else if (f < 256) { W = Wk; B = bk; kind = 1; fo = f - 128; }
    else if (f < 384) { W = Wv; B = bv; kind = 2; fo = f - 256; }
    else              { W = Ws; B = bs; kind = 3; fo = f - 384; }

    float acc[16];
    float bias = B[fo];
    #pragma unroll
    for (int r = 0; r < 16; r++) acc[r] = bias;

    const float4* Wrow = (const float4*)(W + fo * INFEAT);
    #pragma unroll
    for (int kt = 0; kt < 4; kt++) {
        float4 w[8];
        #pragma unroll
        for (int j = 0; j < 8; j++) w[j] = Wrow[kt * 8 + j];
        #pragma unroll
        for (int r = 0; r < 16; r++) {
            float a = acc[r];
            #pragma unroll
            for (int j = 0; j < 8; j++) {
                float4 hv = h_s[r][kt * 8 + j];
                a += hv.x * w[j].x;
                a += hv.y * w[j].y;
                a += hv.z * w[j].z;
                a += hv.w * w[j].w;
            }
            acc[r] = a;
        }
    }

    int head = fo >> 6, d = fo & 63;
    #pragma unroll
    for (int r = 0; r < 16; r++) {
        int n = rowbase + r;
        if (kind == 0)      g_q[head][n][d] = __float2bfloat16(acc[r] * QSCALE);
        else if (kind == 1) g_k[head][n][d] = __float2bfloat16(acc[r]);
        else if (kind == 2) g_v[head][n][d] = __float2bfloat16(acc[r]);
        else                out[(long long)n * 128 + fo] = acc[r];
    }
}

// ---------------------------------------------------------------------------
// Kernel 3: masked flash attention, BM=64, occ 3, split-K x4.
// No-max softmax via ex2 (Q pre-scaled by log2e/8). bf16 mma.sync.
// ---------------------------------------------------------------------------
__device__ __forceinline__ uint32_t s2u(const void* p) {
    return (uint32_t)__cvta_generic_to_shared(p);
}
__device__ __forceinline__ float ex2f(float x) {
    float y; asm("ex2.approx.f32 %0, %1;" : "=f"(y) : "f"(x)); return y;
}

#define CP16(dst, src) asm volatile("cp.async.cg.shared.global [%0], [%1], 16;\n" :: "r"(dst), "l"(src) : "memory")
#define CP4(dst, src)  asm volatile("cp.async.ca.shared.global [%0], [%1], 4;\n"  :: "r"(dst), "l"(src) : "memory")
#define CP_COMMIT()    asm volatile("cp.async.commit_group;\n" ::: "memory")
#define CP_WAIT1()     asm volatile("cp.async.wait_group 1;\n" ::: "memory")
#define CP_WAIT0()     asm volatile("cp.async.wait_group 0;\n" ::: "memory")

__device__ __forceinline__ void ldsm4(uint32_t* d, uint32_t addr) {
    asm volatile("ldmatrix.sync.aligned.m8n8.x4.shared.b16 {%0,%1,%2,%3}, [%4];\n"
        : "=r"(d[0]), "=r"(d[1]), "=r"(d[2]), "=r"(d[3]) : "r"(addr));
}
__device__ __forceinline__ void ldsm4t(uint32_t* d, uint32_t addr) {
    asm volatile("ldmatrix.sync.aligned.m8n8.x4.trans.shared.b16 {%0,%1,%2,%3}, [%4];\n"
        : "=r"(d[0]), "=r"(d[1]), "=r"(d[2]), "=r"(d[3]) : "r"(addr));
}
__device__ __forceinline__ void mma16816(float* c, const uint32_t* a, const uint32_t* b) {
    asm volatile("mma.sync.aligned.m16n8k16.row.col.f32.bf16.bf16.f32 "
        "{%0,%1,%2,%3}, {%4,%5,%6,%7}, {%8,%9}, {%0,%1,%2,%3};\n"
        : "+f"(c[0]), "+f"(c[1]), "+f"(c[2]), "+f"(c[3])
        : "r"(a[0]), "r"(a[1]), "r"(a[2]), "r"(a[3]), "r"(b[0]), "r"(b[1]));
}

__global__ void __launch_bounds__(128, 3) attn_kernel()
{
    int mtile = blockIdx.x, head = blockIdx.y, split = blockIdx.z;
    int t0 = split * TILES_PER_SPLIT;
    int tid = threadIdx.x, warp = tid >> 5, lane = tid & 31;
    int g = lane >> 2, t4 = lane & 3;

    __shared__ __align__(16) __nv_bfloat16 q_s[BM * DHEAD];        // 8 KB, swizzled
    __shared__ __align__(16) __nv_bfloat16 k_s[2][BN * DHEAD];     // 16 KB
    __shared__ __align__(16) __nv_bfloat16 v_s[2][BN * DHEAD];     // 16 KB
    __shared__ uint32_t mask_s[2][BM * 2];                          // 1 KB

    // ---- stage Q tile (LDG -> STS, swizzled: 16B chunk ^ (row&7)) ----
    {
        const uint4* qg = (const uint4*)&g_q[head][mtile * BM][0];
        uint4* q4 = (uint4*)q_s;
        for (int i = tid; i < 512; i += 128) {
            int r = i >> 3, c = i & 7;
            q4[r * 8 + (c ^ (r & 7))] = qg[i];
        }
    }
    __syncthreads();

    // ---- load Q a-frags into registers (resident whole kernel) ----
    uint32_t qf[4][4];
    {
        char* qb = (char*)q_s;
        #pragma unroll
        for (int kt = 0; kt < 4; kt++) {
            int r = warp * 16 + (lane & 15);
            int kc = kt * 2 + (lane >> 4);
            uint32_t addr = s2u(qb + r * 128 + ((kc ^ (r & 7)) << 4));
            ldsm4(qf[kt], addr);
        }
    }

    float o[8][4];
    #pragma unroll
    for (int j = 0; j < 8; j++)
        { o[j][0] = 0.f; o[j][1] = 0.f; o[j][2] = 0.f; o[j][3] = 0.f; }
    float lsum0 = 0.f, lsum1 = 0.f;

    const int rA = warp * 16 + g, rB = rA + 8;

    // ---- prefetch tile t0 ----
    {
        const uint4* kg = (const uint4*)&g_k[head][t0 * BN][0];
        const uint4* vg = (const uint4*)&g_v[head][t0 * BN][0];
        uint4* ks4 = (uint4*)k_s[0];
        uint4* vs4 = (uint4*)v_s[0];
        for (int i = tid; i < 512; i += 128) {
            int r = i >> 3, c = i & 7, dsw = r * 8 + (c ^ (r & 7));
            CP16(s2u(&ks4[dsw]), &kg[i]);
            CP16(s2u(&vs4[dsw]), &vg[i]);
        }
        int row = tid >> 1, w = tid & 1;
        CP4(s2u(&mask_s[0][row * 2 + w]),
            &g_adjbits[(mtile * BM + row) * MASKW + t0 * 2 + w]);
        CP_COMMIT();
    }

    for (int tt = 0; tt < TILES_PER_SPLIT; tt++) {
        int t = t0 + tt;
        int buf = tt & 1;
        __syncthreads();   // prior compute done before overwriting buf^1
        if (tt + 1 < TILES_PER_SPLIT) {
            int n0 = (t + 1) * BN;
            const uint4* kg = (const uint4*)&g_k[head][n0][0];
            const uint4* vg = (const uint4*)&g_v[head][n0][0];
            uint4* ks4 = (uint4*)k_s[buf ^ 1];
            uint4* vs4 = (uint4*)v_s[buf ^ 1];
            for (int i = tid; i < 512; i += 128) {
                int r = i >> 3, c = i & 7, dsw = r * 8 + (c ^ (r & 7));
                CP16(s2u(&ks4[dsw]), &kg[i]);
                CP16(s2u(&vs4[dsw]), &vg[i]);
            }
            int row = tid >> 1, w = tid & 1;
            CP4(s2u(&mask_s[buf ^ 1][row * 2 + w]),
                &g_adjbits[(mtile * BM + row) * MASKW + (t + 1) * 2 + w]);
            CP_COMMIT();
            CP_WAIT1();
        } else {
            CP_WAIT0();
        }
        __syncthreads();   // tile t fully in smem for all threads

        // ---- S = Q * K^T  (q pre-scaled by log2e/8) ----
        float sc[8][4];
        #pragma unroll
        for (int j = 0; j < 8; j++)
            { sc[j][0] = 0.f; sc[j][1] = 0.f; sc[j][2] = 0.f; sc[j][3] = 0.f; }

        char* kb8 = (char*)k_s[buf];
        #pragma unroll
        for (int kt = 0; kt < 4; kt++) {
            uint32_t kb[8][2];
            #pragma unroll
            for (int p = 0; p < 4; p++) {
                int nrow = p * 16 + (lane & 7) + ((lane & 16) ? 8 : 0);
                int kc = kt * 2 + ((lane & 8) ? 1 : 0);
                uint32_t addr = s2u(kb8 + nrow * 128 + ((kc ^ (nrow & 7)) << 4));
                uint32_t r[4]; ldsm4(r, addr);
                kb[2 * p][0] = r[0]; kb[2 * p][1] = r[1];
                kb[2 * p + 1][0] = r[2]; kb[2 * p + 1][1] = r[3];
            }
            #pragma unroll
            for (int j = 0; j < 8; j++) mma16816(sc[j], qf[kt], kb[j]);
        }

        // ---- PV loop with ex2/mask folded in per kt ----
        uint32_t mA0 = mask_s[buf][rA * 2], mA1 = mask_s[buf][rA * 2 + 1];
        uint32_t mB0 = mask_s[buf][rB * 2], mB1 = mask_s[buf][rB * 2 + 1];
        char* vb8 = (char*)v_s[buf];
        #pragma unroll
        for (int kt = 0; kt < 4; kt++) {
            // ex2/mask/pack for S columns j = 2kt, 2kt+1
            uint32_t a[4];
            #pragma unroll
            for (int jj = 0; jj < 2; jj++) {
                int j = 2 * kt + jj;
                int sh = (j * 8 + t4 * 2) & 31;
                uint32_t wA = (j < 4) ? mA0 : mA1;
                uint32_t wB = (j < 4) ? mB0 : mB1;
                float e0 = ((wA >> sh) & 1)       ? ex2f(sc[j][0]) : 0.f;
                float e1 = ((wA >> (sh + 1)) & 1) ? ex2f(sc[j][1]) : 0.f;
                float e2 = ((wB >> sh) & 1)       ? ex2f(sc[j][2]) : 0.f;
                float e3 = ((wB >> (sh + 1)) & 1) ? ex2f(sc[j][3]) : 0.f;
                lsum0 += e0 + e1;
                lsum1 += e2 + e3;
                __nv_bfloat162 p01 = __floats2bfloat162_rn(e0, e1);
                __nv_bfloat162 p23 = __floats2bfloat162_rn(e2, e3);
                a[2 * jj]     = *(uint32_t*)&p01;
                a[2 * jj + 1] = *(uint32_t*)&p23;
            }

            uint32_t vb[8][2];
            #pragma unroll
            for (int p = 0; p < 4; p++) {
                int vrow = kt * 16 + (lane & 7) + ((lane & 8) ? 8 : 0);
                int dc = 2 * p + ((lane & 16) ? 1 : 0);
                uint32_t addr = s2u(vb8 + vrow * 128 + ((dc ^ (vrow & 7)) << 4));
                uint32_t r[4]; ldsm4t(r, addr);
                vb[2 * p][0] = r[0]; vb[2 * p][1] = r[1];
                vb[2 * p + 1][0] = r[2]; vb[2 * p + 1][1] = r[3];
            }
            #pragma unroll
            for (int jd = 0; jd < 8; jd++) mma16816(o[jd], a, vb[jd]);
        }
    }

    // ---- store partial O (unnormalized) + row sums to scratch ----
    lsum0 += __shfl_xor_sync(0xffffffffu, lsum0, 1);
    lsum0 += __shfl_xor_sync(0xffffffffu, lsum0, 2);
    lsum1 += __shfl_xor_sync(0xffffffffu, lsum1, 1);
    lsum1 += __shfl_xor_sync(0xffffffffu, lsum1, 2);

    int nA = mtile * BM + rA;
    int nB = mtile * BM + rB;
    if (t4 == 0) {
        g_lpart[split][head][nA] = lsum0;
        g_lpart[split][head][nB] = lsum1;
    }
    #pragma unroll
    for (int jd = 0; jd < 8; jd++) {
        int d = jd * 8 + t4 * 2;
        *(float2*)&g_opart[split][head][nA][d] = make_float2(o[jd][0], o[jd][1]);
        *(float2*)&g_opart[split][head][nB][d] = make_float2(o[jd][2], o[jd][3]);
    }
}

// ---------------------------------------------------------------------------
// Kernel 4: combine splits, normalize, add skip (already resident in d_out)
// ---------------------------------------------------------------------------
__global__ void __launch_bounds__(256) epilogue_kernel(float* __restrict__ out)
{
    int idx = blockIdx.x * 256 + threadIdx.x;   // float4 index over [8192][128]
    int n = idx >> 5;
    int f4 = idx & 31;
    int head = f4 >> 4;
    int d = (f4 & 15) * 4;

    float4 a = *(const float4*)&g_opart[0][head][n][d];
    float lt = g_lpart[0][head][n];
    #pragma unroll
    for (int s = 1; s < NSPLIT; s++) {
        float4 b = *(const float4*)&g_opart[s][head][n][d];
        a.x += b.x; a.y += b.y; a.z += b.z; a.w += b.w;
        lt += g_lpart[s][head][n];
    }
    float inv = 1.f / lt;
    float4* po = (float4*)out + idx;
    float4 s = *po;
    s.x += a.x * inv;
    s.y += a.y * inv;
    s.z += a.z * inv;
    s.w += a.w * inv;
    *po = s;
}

// ---------------------------------------------------------------------------
extern "C" void kernel_launch(void* const* d_in, const int* in_sizes, int n_in,
                              void* d_out, int out_size)
{
    const float* h   = (const float*)d_in[0];
    const int*   adj = (const int*)d_in[1];
    const float* Wq  = (const float*)d_in[2];
    const float* bq  = (const float*)d_in[3];
    const float* Wk  = (const float*)d_in[4];
    const float* bk  = (const float*)d_in[5];
    const float* Wv  = (const float*)d_in[6];
    const float* bv  = (const float*)d_in[7];
    const float* Ws  = (const float*)d_in[8];
    const float* bs  = (const float*)d_in[9];
    float* out = (float*)d_out;

    // 1) pack adjacency bitmask (high-occupancy, low-reg)
    pack_kernel<<<NTOK * MASKW / (8 * 32), 256>>>(adj);

    // 2) slim projections (writes skip into d_out, Q/K/V to device buffers)
    proj_kernel<<<1024, 256>>>(h, Wq, bq, Wk, bk, Wv, bv, Ws, bs, out);

    // 3) masked flash attention, split-K x4, occ 3, partials to scratch
    dim3 grid(NTOK / BM, NHEADS, NSPLIT);
    attn_kernel<<<grid, 128>>>();

    // 4) combine + normalize + skip
    epilogue_kernel<<<(NTOK * 128 / 4) / 256, 256>>>(out);
}

// round 16
// speedup vs baseline: 1.1169x; 1.0451x over previous
#include <cuda_runtime.h>
#include <cuda_bf16.h>
#include <cstdint>

#define NTOK   8192
#define INFEAT 128
#define DHEAD  64
#define NHEADS 2
#define MASKW  (NTOK/32)   // 256 words per row

#define BM 64
#define BN 64
#define NTILES (NTOK/BN)   // 128
#define NSPLIT 4
#define TILES_PER_SPLIT (NTILES/NSPLIT)  // 32

// 0.125 * log2(e): folds the 1/sqrt(64) scale and the exp->exp2 change of base
#define QSCALE 0.1803368801111204f

__device__ __align__(16) uint32_t      g_adjbits[NTOK * MASKW];              // 8 MB
__device__ __align__(16) __nv_bfloat16 g_q[NHEADS][NTOK][DHEAD];             // 2 MB
__device__ __align__(16) __nv_bfloat16 g_k[NHEADS][NTOK][DHEAD];             // 2 MB
__device__ __align__(16) __nv_bfloat16 g_v[NHEADS][NTOK][DHEAD];             // 2 MB
__device__ __align__(16) float         g_opart[NSPLIT][NHEADS][NTOK][DHEAD]; // 16 MB
__device__ __align__(16) float         g_lpart[NSPLIT][NHEADS][NTOK];        // 256 KB

// ---------------------------------------------------------------------------
// Kernel 1: pack adjacency -> bitmask. Standalone, low-reg, high-occupancy.
// ---------------------------------------------------------------------------
__global__ void __launch_bounds__(256) pack_kernel(const int* __restrict__ adj)
{
    int gwarp = blockIdx.x * 8 + (threadIdx.x >> 5);
    int lane = threadIdx.x & 31;
    long long base = (long long)gwarp * 1024;

    #pragma unroll
    for (int it = 0; it < 2; it++) {
        const int* p = adj + base + it * 512 + lane;
        int v[16];
        #pragma unroll
        for (int j = 0; j < 16; j++) v[j] = p[j * 32];   // MLP=16, 1 line/instr
        uint32_t myword = 0;
        #pragma unroll
        for (int j = 0; j < 16; j++) {
            uint32_t b = __ballot_sync(0xffffffffu, v[j] > 0);
            if (lane == j) myword = b;
        }
        if (lane < 16)
            g_adjbits[gwarp * 32 + it * 16 + lane] = myword;
    }
}

// ---------------------------------------------------------------------------
// Kernel 2: slim projections. 256 thr; block = 16 rows x 256 features.
// f in [0,512): Q(*QSCALE,bf16) | K(bf16) | V(bf16) | skip(fp32 -> d_out)
// ---------------------------------------------------------------------------
__global__ void __launch_bounds__(256) proj_kernel(
    const float* __restrict__ h,
    const float* __restrict__ Wq, const float* __restrict__ bq,
    const float* __restrict__ Wk, const float* __restrict__ bk,
    const float* __restrict__ Wv, const float* __restrict__ bv,
    const float* __restrict__ Ws, const float* __restrict__ bs,
    float* __restrict__ out)
{
    __shared__ float4 h_s[16][32];   // 8 KB
    int tid = threadIdx.x;
    int rowbase = (blockIdx.x >> 1) * 16;
    int fhalf = blockIdx.x & 1;

    const float4* h4 = (const float4*)(h + (long long)rowbase * INFEAT);
    for (int i = tid; i < 16 * 32; i += 256)
        h_s[i >> 5][i & 31] = h4[i];
    __syncthreads();

    int f = fhalf * 256 + tid;           // 0..511
    const float* W; const float* B; int kind, fo;
    if (f < 128)      { W = Wq; B = bq; kind = 0; fo = f; }
    else if (f < 256) { W = Wk; B = bk; kind = 1; fo = f - 128; }
    else if (f < 384) { W = Wv; B = bv; kind = 2; fo = f - 256; }
    else              { W = Ws; B = bs; kind = 3; fo = f - 384; }

    float acc[16];
    float bias = B[fo];
    #pragma unroll
    for (int r = 0; r < 16; r++) acc[r] = bias;

    const float4* Wrow = (const float4*)(W + fo * INFEAT);
    #pragma unroll
    for (int kt = 0; kt < 4; kt++) {
        float4 w[8];
        #pragma unroll
        for (int j = 0; j < 8; j++) w[j] = Wrow[kt * 8 + j];
        #pragma unroll
        for (int r = 0; r < 16; r++) {
            float a = acc[r];
            #pragma unroll
            for (int j = 0; j < 8; j++) {
                float4 hv = h_s[r][kt * 8 + j];
                a += hv.x * w[j].x;
                a += hv.y * w[j].y;
                a += hv.z * w[j].z;
                a += hv.w * w[j].w;
            }
            acc[r] = a;
        }
    }

    int head = fo >> 6, d = fo & 63;
    #pragma unroll
    for (int r = 0; r < 16; r++) {
        int n = rowbase + r;
        if (kind == 0)      g_q[head][n][d] = __float2bfloat16(acc[r] * QSCALE);
        else if (kind == 1) g_k[head][n][d] = __float2bfloat16(acc[r]);
        else if (kind == 2) g_v[head][n][d] = __float2bfloat16(acc[r]);
        else                out[(long long)n * 128 + fo] = acc[r];
    }
}

// ---------------------------------------------------------------------------
// Kernel 3: masked flash attention, BM=64, occ 4 (measured best), split-K x4.
// No-max softmax via ex2 (Q pre-scaled by log2e/8). bf16 mma.sync.
// ---------------------------------------------------------------------------
__device__ __forceinline__ uint32_t s2u(const void* p) {
    return (uint32_t)__cvta_generic_to_shared(p);
}
__device__ __forceinline__ float ex2f(float x) {
    float y; asm("ex2.approx.f32 %0, %1;" : "=f"(y) : "f"(x)); return y;
}

#define CP16(dst, src) asm volatile("cp.async.cg.shared.global [%0], [%1], 16;\n" :: "r"(dst), "l"(src) : "memory")
#define CP4(dst, src)  asm volatile("cp.async.ca.shared.global [%0], [%1], 4;\n"  :: "r"(dst), "l"(src) : "memory")
#define CP_COMMIT()    asm volatile("cp.async.commit_group;\n" ::: "memory")
#define CP_WAIT1()     asm volatile("cp.async.wait_group 1;\n" ::: "memory")
#define CP_WAIT0()     asm volatile("cp.async.wait_group 0;\n" ::: "memory")

__device__ __forceinline__ void ldsm4(uint32_t* d, uint32_t addr) {
    asm volatile("ldmatrix.sync.aligned.m8n8.x4.shared.b16 {%0,%1,%2,%3}, [%4];\n"
        : "=r"(d[0]), "=r"(d[1]), "=r"(d[2]), "=r"(d[3]) : "r"(addr));
}
__device__ __forceinline__ void ldsm4t(uint32_t* d, uint32_t addr) {
    asm volatile("ldmatrix.sync.aligned.m8n8.x4.trans.shared.b16 {%0,%1,%2,%3}, [%4];\n"
        : "=r"(d[0]), "=r"(d[1]), "=r"(d[2]), "=r"(d[3]) : "r"(addr));
}
__device__ __forceinline__ void mma16816(float* c, const uint32_t* a, const uint32_t* b) {
    asm volatile("mma.sync.aligned.m16n8k16.row.col.f32.bf16.bf16.f32 "
        "{%0,%1,%2,%3}, {%4,%5,%6,%7}, {%8,%9}, {%0,%1,%2,%3};\n"
        : "+f"(c[0]), "+f"(c[1]), "+f"(c[2]), "+f"(c[3])
        : "r"(a[0]), "r"(a[1]), "r"(a[2]), "r"(a[3]), "r"(b[0]), "r"(b[1]));
}

__global__ void __launch_bounds__(128, 4) attn_kernel()
{
    int mtile = blockIdx.x, head = blockIdx.y, split = blockIdx.z;
    int t0 = split * TILES_PER_SPLIT;
    int tid = threadIdx.x, warp = tid >> 5, lane = tid & 31;
    int g = lane >> 2, t4 = lane & 3;

    __shared__ __align__(16) __nv_bfloat16 q_s[BM * DHEAD];        // 8 KB, swizzled
    __shared__ __align__(16) __nv_bfloat16 k_s[2][BN * DHEAD];     // 16 KB
    __shared__ __align__(16) __nv_bfloat16 v_s[2][BN * DHEAD];     // 16 KB
    __shared__ uint32_t mask_s[2][BM * 2];                          // 1 KB

    // ---- stage Q tile (LDG -> STS, swizzled: 16B chunk ^ (row&7)) ----
    {
        const uint4* qg = (const uint4*)&g_q[head][mtile * BM][0];
        uint4* q4 = (uint4*)q_s;
        for (int i = tid; i < 512; i += 128) {
            int r = i >> 3, c = i & 7;
            q4[r * 8 + (c ^ (r & 7))] = qg[i];
        }
    }
    __syncthreads();

    // ---- load Q a-frags into registers (resident whole kernel) ----
    uint32_t qf[4][4];
    {
        char* qb = (char*)q_s;
        #pragma unroll
        for (int kt = 0; kt < 4; kt++) {
            int r = warp * 16 + (lane & 15);
            int kc = kt * 2 + (lane >> 4);
            uint32_t addr = s2u(qb + r * 128 + ((kc ^ (r & 7)) << 4));
            ldsm4(qf[kt], addr);
        }
    }

    float o[8][4];
    #pragma unroll
    for (int j = 0; j < 8; j++)
        { o[j][0] = 0.f; o[j][1] = 0.f; o[j][2] = 0.f; o[j][3] = 0.f; }
    float lsum0 = 0.f, lsum1 = 0.f;

    const int rA = warp * 16 + g, rB = rA + 8;

    // ---- prefetch tile t0 ----
    {
        const uint4* kg = (const uint4*)&g_k[head][t0 * BN][0];
        const uint4* vg = (const uint4*)&g_v[head][t0 * BN][0];
        uint4* ks4 = (uint4*)k_s[0];
        uint4* vs4 = (uint4*)v_s[0];
        for (int i = tid; i < 512; i += 128) {
            int r = i >> 3, c = i & 7, dsw = r * 8 + (c ^ (r & 7));
            CP16(s2u(&ks4[dsw]), &kg[i]);
            CP16(s2u(&vs4[dsw]), &vg[i]);
        }
        int row = tid >> 1, w = tid & 1;
        CP4(s2u(&mask_s[0][row * 2 + w]),
            &g_adjbits[(mtile * BM + row) * MASKW + t0 * 2 + w]);
        CP_COMMIT();
    }

    for (int tt = 0; tt < TILES_PER_SPLIT; tt++) {
        int t = t0 + tt;
        int buf = tt & 1;
        __syncthreads();   // prior compute done before overwriting buf^1
        if (tt + 1 < TILES_PER_SPLIT) {
            int n0 = (t + 1) * BN;
            const uint4* kg = (const uint4*)&g_k[head][n0][0];
            const uint4* vg = (const uint4*)&g_v[head][n0][0];
            uint4* ks4 = (uint4*)k_s[buf ^ 1];
            uint4* vs4 = (uint4*)v_s[buf ^ 1];
            for (int i = tid; i < 512; i += 128) {
                int r = i >> 3, c = i & 7, dsw = r * 8 + (c ^ (r & 7));
                CP16(s2u(&ks4[dsw]), &kg[i]);
                CP16(s2u(&vs4[dsw]), &vg[i]);
            }
            int row = tid >> 1, w = tid & 1;
            CP4(s2u(&mask_s[buf ^ 1][row * 2 + w]),
                &g_adjbits[(mtile * BM + row) * MASKW + (t + 1) * 2 + w]);
            CP_COMMIT();
            CP_WAIT1();
        } else {
            CP_WAIT0();
        }
        __syncthreads();   // tile t fully in smem for all threads

        // ---- S = Q * K^T  (q pre-scaled by log2e/8) ----
        float sc[8][4];
        #pragma unroll
        for (int j = 0; j < 8; j++)
            { sc[j][0] = 0.f; sc[j][1] = 0.f; sc[j][2] = 0.f; sc[j][3] = 0.f; }

        char* kb8 = (char*)k_s[buf];
        #pragma unroll
        for (int kt = 0; kt < 4; kt++) {
            uint32_t kb[8][2];
            #pragma unroll
            for (int p = 0; p < 4; p++) {
                int nrow = p * 16 + (lane & 7) + ((lane & 16) ? 8 : 0);
                int kc = kt * 2 + ((lane & 8) ? 1 : 0);
                uint32_t addr = s2u(kb8 + nrow * 128 + ((kc ^ (nrow & 7)) << 4));
                uint32_t r[4]; ldsm4(r, addr);
                kb[2 * p][0] = r[0]; kb[2 * p][1] = r[1];
                kb[2 * p + 1][0] = r[2]; kb[2 * p + 1][1] = r[3];
            }
            #pragma unroll
            for (int j = 0; j < 8; j++) mma16816(sc[j], qf[kt], kb[j]);
        }

        // ---- PV loop with ex2/mask folded in per kt ----
        uint32_t mA0 = mask_s[buf][rA * 2], mA1 = mask_s[buf][rA * 2 + 1];
        uint32_t mB0 = mask_s[buf][rB * 2], mB1 = mask_s[buf][rB * 2 + 1];
        char* vb8 = (char*)v_s[buf];
        #pragma unroll
        for (int kt = 0; kt < 4; kt++) {
            // ex2/mask/pack for S columns j = 2kt, 2kt+1
            uint32_t a[4];
            #pragma unroll
            for (int jj = 0; jj < 2; jj++) {
                int j = 2 * kt + jj;
                int sh = (j * 8 + t4 * 2) & 31;
                uint32_t wA = (j < 4) ? mA0 : mA1;
                uint32_t wB = (j < 4) ? mB0 : mB1;
                float e0 = ((wA >> sh) & 1)       ? ex2f(sc[j][0]) : 0.f;
                float e1 = ((wA >> (sh + 1)) & 1) ? ex2f(sc[j][1]) : 0.f;
                float e2 = ((wB >> sh) & 1)       ? ex2f(sc[j][2]) : 0.f;
                float e3 = ((wB >> (sh + 1)) & 1) ? ex2f(sc[j][3]) : 0.f;
                lsum0 += e0 + e1;
                lsum1 += e2 + e3;
                __nv_bfloat162 p01 = __floats2bfloat162_rn(e0, e1);
                __nv_bfloat162 p23 = __floats2bfloat162_rn(e2, e3);
                a[2 * jj]     = *(uint32_t*)&p01;
                a[2 * jj + 1] = *(uint32_t*)&p23;
            }

            uint32_t vb[8][2];
            #pragma unroll
            for (int p = 0; p < 4; p++) {
                int vrow = kt * 16 + (lane & 7) + ((lane & 8) ? 8 : 0);
                int dc = 2 * p + ((lane & 16) ? 1 : 0);
                uint32_t addr = s2u(vb8 + vrow * 128 + ((dc ^ (vrow & 7)) << 4));
                uint32_t r[4]; ldsm4t(r, addr);
                vb[2 * p][0] = r[0]; vb[2 * p][1] = r[1];
                vb[2 * p + 1][0] = r[2]; vb[2 * p + 1][1] = r[3];
            }
            #pragma unroll
            for (int jd = 0; jd < 8; jd++) mma16816(o[jd], a, vb[jd]);
        }
    }

    // ---- store partial O (unnormalized) + row sums to scratch ----
    lsum0 += __shfl_xor_sync(0xffffffffu, lsum0, 1);
    lsum0 += __shfl_xor_sync(0xffffffffu, lsum0, 2);
    lsum1 += __shfl_xor_sync(0xffffffffu, lsum1, 1);
    lsum1 += __shfl_xor_sync(0xffffffffu, lsum1, 2);

    int nA = mtile * BM + rA;
    int nB = mtile * BM + rB;
    if (t4 == 0) {
        g_lpart[split][head][nA] = lsum0;
        g_lpart[split][head][nB] = lsum1;
    }
    #pragma unroll
    for (int jd = 0; jd < 8; jd++) {
        int d = jd * 8 + t4 * 2;
        *(float2*)&g_opart[split][head][nA][d] = make_float2(o[jd][0], o[jd][1]);
        *(float2*)&g_opart[split][head][nB][d] = make_float2(o[jd][2], o[jd][3]);
    }
}

// ---------------------------------------------------------------------------
// Kernel 4: combine splits, normalize, add skip (already resident in d_out)
// ---------------------------------------------------------------------------
__global__ void __launch_bounds__(256) epilogue_kernel(float* __restrict__ out)
{
    int idx = blockIdx.x * 256 + threadIdx.x;   // float4 index over [8192][128]
    int n = idx >> 5;
    int f4 = idx & 31;
    int head = f4 >> 4;
    int d = (f4 & 15) * 4;

    float4 a = *(const float4*)&g_opart[0][head][n][d];
    float lt = g_lpart[0][head][n];
    #pragma unroll
    for (int s = 1; s < NSPLIT; s++) {
        float4 b = *(const float4*)&g_opart[s][head][n][d];
        a.x += b.x; a.y += b.y; a.z += b.z; a.w += b.w;
        lt += g_lpart[s][head][n];
    }
    float inv = 1.f / lt;
    float4* po = (float4*)out + idx;
    float4 s = *po;
    s.x += a.x * inv;
    s.y += a.y * inv;
    s.z += a.z * inv;
    s.w += a.w * inv;
    *po = s;
}

// ---------------------------------------------------------------------------
extern "C" void kernel_launch(void* const* d_in, const int* in_sizes, int n_in,
                              void* d_out, int out_size)
{
    const float* h   = (const float*)d_in[0];
    const int*   adj = (const int*)d_in[1];
    const float* Wq  = (const float*)d_in[2];
    const float* bq  = (const float*)d_in[3];
    const float* Wk  = (const float*)d_in[4];
    const float* bk  = (const float*)d_in[5];
    const float* Wv  = (const float*)d_in[6];
    const float* bv  = (const float*)d_in[7];
    const float* Ws  = (const float*)d_in[8];
    const float* bs  = (const float*)d_in[9];
    float* out = (float*)d_out;

    // one-time host-side handles (no device memory; same work every call)
    static cudaStream_t s_side = []() {
        cudaStream_t s; cudaStreamCreateWithFlags(&s, cudaStreamNonBlocking); return s;
    }();
    static cudaEvent_t ev_fork = []() {
        cudaEvent_t e; cudaEventCreateWithFlags(&e, cudaEventDisableTiming); return e;
    }();
    static cudaEvent_t ev_join = []() {
        cudaEvent_t e; cudaEventCreateWithFlags(&e, cudaEventDisableTiming); return e;
    }();

    // fork: pack (memory-bound) on side stream, proj (FMA-bound) on main
    cudaEventRecord(ev_fork, 0);
    cudaStreamWaitEvent(s_side, ev_fork, 0);

    pack_kernel<<<NTOK * MASKW / (8 * 32), 256, 0, s_side>>>(adj);
    proj_kernel<<<1024, 256>>>(h, Wq, bq, Wk, bk, Wv, bv, Ws, bs, out);

    // join before attention (needs both adjbits and q/k/v)
    cudaEventRecord(ev_join, s_side);
    cudaStreamWaitEvent(0, ev_join, 0);

    // masked flash attention, split-K x4, occ 4, partials to scratch
    dim3 grid(NTOK / BM, NHEADS, NSPLIT);
    attn_kernel<<<grid, 128>>>();

    // combine + normalize + skip
    epilogue_kernel<<<(NTOK * 128 / 4) / 256, 256>>>(out);
}